// round 10
// baseline (speedup 1.0000x reference)
#include <cuda_runtime.h>
#include <math.h>

// Problem constants (B=2048, N=150; B derived from in_sizes)
#define NPART    150
#define ROWP     152
#define COLP     156            // A row stride: conflict-free rows AND column walks
#define NCH      38             // float4 chunks covering [0,152)
#define RCH      19             // float4 chunks per half-row (76 floats)
#define NTHREADS 320            // mult phase: 152 rows x 2 halves = 304 active
#define ITERS    100
#define PEEL2    6
#define PEEL     10
#define ABSORB_PERIOD 15
#define EPSR     1e-16f
#define INV_ELN2 28.853900817779268f   // 1/(0.05*ln2)
#define ELN2     0.034657359027997264f // 0.05*ln2  (C_nat = A * ELN2)
#define YPAD     1.0e4f

__device__ float g_batch[8192];

__device__ __forceinline__ float ex2f(float x) {
    float r; asm("ex2.approx.ftz.f32 %0, %1;" : "=f"(r) : "f"(x)); return r;
}
__device__ __forceinline__ float lg2f_(float x) {
    float r; asm("lg2.approx.f32 %0, %1;" : "=f"(r) : "f"(x)); return r;
}

// block sum for NTHREADS=320
__device__ __forceinline__ float block_sum(float v, float* red, int tid) {
    red[tid] = v;
    __syncthreads();
    if (tid < 64) red[tid] += red[tid + 256];
    __syncthreads();
    #pragma unroll
    for (int s = 128; s > 0; s >>= 1) {
        if (tid < s) red[tid] += red[tid + s];
        __syncthreads();
    }
    float r = red[0];
    __syncthreads();
    return r;
}

extern __shared__ float smem[];

__global__ void __launch_bounds__(NTHREADS, 1)
sinkhorn_kernel(const float* __restrict__ p_rec, const float* __restrict__ p_tar)
{
    float* SC  = smem;                  // ROWP*COLP: cost matrix A — PERSISTS all phases
    float* G2  = SC  + ROWP * COLP;
    float* F2  = G2  + ROWP;
    float* la2 = F2  + ROWP;
    float* lb2 = la2 + ROWP;
    float* Mf  = lb2 + ROWP;            // warm centers; reused as uu after peel
    float* Mg  = Mf  + ROWP;            // reused as vv
    float* xe  = Mg  + ROWP;
    float* xp  = xe  + ROWP;
    float* ye  = xp  + ROWP;
    float* yp  = ye  + ROWP;
    float* aL  = yp  + ROWP;
    float* bL  = aL  + ROWP;
    float* red = bL  + ROWP;            // NTHREADS floats

    const int b   = blockIdx.x;
    const int tid = threadIdx.x;
    const float PI_F  = 3.14159265358979323846f;
    const float TWOPI = 6.28318530717958647692f;

    // ---- load particles ----
    float px = 0.f, py = 0.f, pz = 0.f, qx = 0.f, qy = 0.f, qz = 0.f;
    if (tid < NPART) {
        const float* p = p_rec + (size_t)b * NPART * 3 + tid * 3;
        px = p[0]; py = p[1]; pz = p[2];
        const float* q = p_tar + (size_t)b * NPART * 3 + tid * 3;
        qx = q[0]; qy = q[1]; qz = q[2];
    }

    // ---- jet sums ----
    float jx = block_sum(px, red, tid);
    float jy = block_sum(py, red, tid);
    float jz = block_sum(pz, red, tid);
    float kx = block_sum(qx, red, tid);
    float ky = block_sum(qy, red, tid);
    float kz = block_sum(qz, red, tid);

    // ---- polar-rel coordinates ----
    float jpt  = sqrtf(jx * jx + jy * jy + EPSR);
    float jphi = atan2f(jy + EPSR, jx + EPSR);
    float jeta = asinhf(jz / (jpt + EPSR));
    float kpt  = sqrtf(kx * kx + ky * ky + EPSR);
    float kphi = atan2f(ky + EPSR, kx + EPSR);
    float keta = asinhf(kz / (kpt + EPSR));

    float ppt  = sqrtf(px * px + py * py + EPSR);
    float pphi = atan2f(py + EPSR, px + EPSR);
    float peta = asinhf(pz / (ppt + EPSR));
    float qpt  = sqrtf(qx * qx + qy * qy + EPSR);
    float qphi = atan2f(qy + EPSR, qx + EPSR);
    float qeta = asinhf(qz / (qpt + EPSR));

    float per = peta - jeta;
    float dpp = pphi - jphi + PI_F;
    float ppr = fmodf(dpp, TWOPI); if (ppr < 0.f) ppr += TWOPI; ppr -= PI_F;
    float pptr = ppt / (jpt + EPSR);

    float qer = qeta - keta;
    float dqq = qphi - kphi + PI_F;
    float qpr = fmodf(dqq, TWOPI); if (qpr < 0.f) qpr += TWOPI; qpr -= PI_F;
    float qptr = qpt / (kpt + EPSR);

    // ---- normalized marginals ----
    float Sa = block_sum(tid < NPART ? pptr : 0.f, red, tid);
    float Sb = block_sum(tid < NPART ? qptr : 0.f, red, tid);

    if (tid < NPART) {
        xe[tid] = per;  xp[tid] = ppr;
        ye[tid] = qer;  yp[tid] = qpr;
        float av = pptr / (Sa + EPSR) + EPSR;
        float bv = qptr / (Sb + EPSR) + EPSR;
        aL[tid]  = av;  bL[tid] = bv;
        la2[tid] = lg2f_(av);
        lb2[tid] = lg2f_(bv);
    } else if (tid < ROWP) {
        xe[tid] = YPAD; xp[tid] = YPAD;
        ye[tid] = YPAD; yp[tid] = YPAD;
        aL[tid] = 1.f;  bL[tid] = 1.f;
        la2[tid] = 0.f; lb2[tid] = 0.f;
    }
    if (tid < ROWP) { G2[tid] = 0.f; F2[tid] = 0.f; Mf[tid] = 0.f; Mg[tid] = 0.f; }
    __syncthreads();

    // ---- cost matrix A (pad = 1e30; persists through the whole kernel) ----
    for (int idx = tid; idx < ROWP * COLP; idx += NTHREADS) {
        int i = idx / COLP;
        int j = idx - i * COLP;
        float v = 1e30f;
        if (i < NPART && j < NPART) {
            float de = xe[i] - ye[j];
            float dp = xp[i] - yp[j];
            v = sqrtf(de * de + dp * dp + EPSR) * INV_ELN2;
        }
        SC[idx] = v;
    }
    __syncthreads();

    // ================= Phase 1: log-domain peel (identical math to R4/R9) =================
    for (int it = 0; it < PEEL; ++it) {
        const bool twopass = (it < PEEL2);

        if (tid < NPART) {
            const float4* crow = (const float4*)(SC + tid * COLP);
            const float4* gp   = (const float4*)G2;
            if (twopass) {
                float m0 = -3.4e38f, m1 = -3.4e38f, m2 = -3.4e38f, m3 = -3.4e38f;
                #pragma unroll 2
                for (int k = 0; k < NCH; ++k) {
                    float4 c = crow[k]; float4 g = gp[k];
                    m0 = fmaxf(m0, g.x - c.x); m1 = fmaxf(m1, g.y - c.y);
                    m2 = fmaxf(m2, g.z - c.z); m3 = fmaxf(m3, g.w - c.w);
                }
                float m = fmaxf(fmaxf(m0, m1), fmaxf(m2, m3));
                float s0 = 0.f, s1 = 0.f, s2 = 0.f, s3 = 0.f;
                #pragma unroll 2
                for (int k = 0; k < NCH; ++k) {
                    float4 c = crow[k]; float4 g = gp[k];
                    s0 += ex2f(g.x - c.x - m); s1 += ex2f(g.y - c.y - m);
                    s2 += ex2f(g.z - c.z - m); s3 += ex2f(g.w - c.w - m);
                }
                F2[tid] = la2[tid] - (m + lg2f_((s0 + s1) + (s2 + s3)));
                Mf[tid] = m;
            } else {
                float m = Mf[tid];
                float m0 = -3.4e38f, m1 = -3.4e38f, m2 = -3.4e38f, m3 = -3.4e38f;
                float s0 = 0.f, s1 = 0.f, s2 = 0.f, s3 = 0.f;
                #pragma unroll 2
                for (int k = 0; k < NCH; ++k) {
                    float4 c = crow[k]; float4 g = gp[k];
                    float t0 = g.x - c.x, t1 = g.y - c.y;
                    float t2 = g.z - c.z, t3 = g.w - c.w;
                    m0 = fmaxf(m0, t0); s0 += ex2f(t0 - m);
                    m1 = fmaxf(m1, t1); s1 += ex2f(t1 - m);
                    m2 = fmaxf(m2, t2); s2 += ex2f(t2 - m);
                    m3 = fmaxf(m3, t3); s3 += ex2f(t3 - m);
                }
                float s = fmaxf((s0 + s1) + (s2 + s3), 1e-30f);
                F2[tid] = la2[tid] - (m + lg2f_(s));
                Mf[tid] = fmaxf(fmaxf(m0, m1), fmaxf(m2, m3));
            }
        }
        __syncthreads();

        if (tid < NPART) {
            const float*  ccol = SC + tid;
            const float4* fp   = (const float4*)F2;
            if (twopass) {
                float m0 = -3.4e38f, m1 = -3.4e38f, m2 = -3.4e38f, m3 = -3.4e38f;
                #pragma unroll 2
                for (int k = 0; k < NCH; ++k) {
                    float4 f = fp[k];
                    const float* cb = ccol + 4 * k * COLP;
                    m0 = fmaxf(m0, f.x - cb[0]);
                    m1 = fmaxf(m1, f.y - cb[COLP]);
                    m2 = fmaxf(m2, f.z - cb[2 * COLP]);
                    m3 = fmaxf(m3, f.w - cb[3 * COLP]);
                }
                float m = fmaxf(fmaxf(m0, m1), fmaxf(m2, m3));
                float s0 = 0.f, s1 = 0.f, s2 = 0.f, s3 = 0.f;
                #pragma unroll 2
                for (int k = 0; k < NCH; ++k) {
                    float4 f = fp[k];
                    const float* cb = ccol + 4 * k * COLP;
                    s0 += ex2f(f.x - cb[0]        - m);
                    s1 += ex2f(f.y - cb[COLP]     - m);
                    s2 += ex2f(f.z - cb[2 * COLP] - m);
                    s3 += ex2f(f.w - cb[3 * COLP] - m);
                }
                G2[tid] = lb2[tid] - (m + lg2f_((s0 + s1) + (s2 + s3)));
                Mg[tid] = m;
            } else {
                float m = Mg[tid];
                float m0 = -3.4e38f, m1 = -3.4e38f, m2 = -3.4e38f, m3 = -3.4e38f;
                float s0 = 0.f, s1 = 0.f, s2 = 0.f, s3 = 0.f;
                #pragma unroll 2
                for (int k = 0; k < NCH; ++k) {
                    float4 f = fp[k];
                    const float* cb = ccol + 4 * k * COLP;
                    float t0 = f.x - cb[0];
                    float t1 = f.y - cb[COLP];
                    float t2 = f.z - cb[2 * COLP];
                    float t3 = f.w - cb[3 * COLP];
                    m0 = fmaxf(m0, t0); s0 += ex2f(t0 - m);
                    m1 = fmaxf(m1, t1); s1 += ex2f(t1 - m);
                    m2 = fmaxf(m2, t2); s2 += ex2f(t2 - m);
                    m3 = fmaxf(m3, t3); s3 += ex2f(t3 - m);
                }
                float s = fmaxf((s0 + s1) + (s2 + s3), 1e-30f);
                G2[tid] = lb2[tid] - (m + lg2f_(s));
                Mg[tid] = fmaxf(fmaxf(m0, m1), fmaxf(m2, m3));
            }
        }
        __syncthreads();
    }

    float* uu = Mf;     // reuse warm-center arrays as fp32 u/v
    float* vv = Mg;
    if (tid < ROWP) { uu[tid] = 1.f; vv[tid] = 1.f; }
    __syncthreads();

    // ---- mult-phase mapping: 2 threads per row/column ----
    const int rw  = tid >> 1;                          // 0..159
    const int hf  = tid & 1;                           // half: index range [hf*76, hf*76+76)
    const int rwc = (rw < ROWP - 1) ? rw : (ROWP - 1); // clamp keeps lanes converged

    // ---- register caches: pr = P[rw][hf-half], pt = P[hf-half][rw] (column) ----
    float4 pr[RCH];     // row slice:    P[rw][j],  j = hf*76 + 4k + {0..3}
    float4 pt[RCH];     // column slice: P[i][rw],  i = hf*76 + 4k + {0..3}
    {
        const float4* arow = (const float4*)(SC + rwc * COLP) + hf * RCH;
        const float4* g4   = ((const float4*)G2) + hf * RCH;
        const float4* f4   = ((const float4*)F2) + hf * RCH;
        const float*  acol = SC + rwc + (hf * 76) * COLP;
        float fi = F2[rwc];
        float gj = G2[rwc];
        #pragma unroll
        for (int k = 0; k < RCH; ++k) {
            float4 a = arow[k]; float4 g = g4[k]; float4 f = f4[k];
            pr[k].x = ex2f(fi + g.x - a.x);   // pad entries: A=1e30 -> 0
            pr[k].y = ex2f(fi + g.y - a.y);
            pr[k].z = ex2f(fi + g.z - a.z);
            pr[k].w = ex2f(fi + g.w - a.w);
            const float* ab = acol + 4 * k * COLP;
            pt[k].x = ex2f(f.x + gj - ab[0]);
            pt[k].y = ex2f(f.y + gj - ab[COLP]);
            pt[k].z = ex2f(f.z + gj - ab[2 * COLP]);
            pt[k].w = ex2f(f.w + gj - ab[3 * COLP]);
        }
    }
    __syncthreads();

    // ================= Phase 2: register-resident multiplicative iterations =================
    for (int it = PEEL; it < ITERS; ++it) {
        // ---- u-update: u_i = a_i / sum_j P[i][j] v_j  (registers + broadcast v) ----
        {
            const float4* v4 = ((const float4*)vv) + hf * RCH;
            float r0 = 0.f, r1 = 0.f, r2 = 0.f, r3 = 0.f;
            #pragma unroll
            for (int k = 0; k < RCH; ++k) {
                float4 p = pr[k]; float4 w = v4[k];
                r0 += p.x * w.x; r1 += p.y * w.y;
                r2 += p.z * w.z; r3 += p.w * w.w;
            }
            float r = (r0 + r1) + (r2 + r3);
            r += __shfl_xor_sync(0xFFFFFFFF, r, 1);
            if (hf == 0 && rw < NPART) uu[rw] = __fdividef(aL[rw], r);
        }
        __syncthreads();

        // ---- v-update: v_j = b_j / sum_i P[i][j] u_i  (registers + broadcast u) ----
        {
            const float4* u4 = ((const float4*)uu) + hf * RCH;
            float c0 = 0.f, c1 = 0.f, c2 = 0.f, c3 = 0.f;
            #pragma unroll
            for (int k = 0; k < RCH; ++k) {
                float4 p = pt[k]; float4 w = u4[k];
                c0 += p.x * w.x; c1 += p.y * w.y;
                c2 += p.z * w.z; c3 += p.w * w.w;
            }
            float c = (c0 + c1) + (c2 + c3);
            c += __shfl_xor_sync(0xFFFFFFFF, c, 1);
            if (hf == 0 && rw < NPART) vv[rw] = __fdividef(bL[rw], c);
        }
        __syncthreads();

        // ---- absorption every 15 iters: fold u,v into F2,G2; rebuild register P ----
        if ((it % ABSORB_PERIOD) == (ABSORB_PERIOD - 1) && it < ITERS - 1) {
            if (tid < NPART) {
                F2[tid] += lg2f_(uu[tid]);
                G2[tid] += lg2f_(vv[tid]);
            }
            __syncthreads();
            {
                const float4* arow = (const float4*)(SC + rwc * COLP) + hf * RCH;
                const float4* g4   = ((const float4*)G2) + hf * RCH;
                const float4* f4   = ((const float4*)F2) + hf * RCH;
                const float*  acol = SC + rwc + (hf * 76) * COLP;
                float fi = F2[rwc];
                float gj = G2[rwc];
                #pragma unroll
                for (int k = 0; k < RCH; ++k) {
                    float4 a = arow[k]; float4 g = g4[k]; float4 f = f4[k];
                    pr[k].x = ex2f(fi + g.x - a.x);
                    pr[k].y = ex2f(fi + g.y - a.y);
                    pr[k].z = ex2f(fi + g.z - a.z);
                    pr[k].w = ex2f(fi + g.w - a.w);
                    const float* ab = acol + 4 * k * COLP;
                    pt[k].x = ex2f(f.x + gj - ab[0]);
                    pt[k].y = ex2f(f.y + gj - ab[COLP]);
                    pt[k].z = ex2f(f.z + gj - ab[2 * COLP]);
                    pt[k].w = ex2f(f.w + gj - ab[3 * COLP]);
                }
            }
            __syncthreads();
            if (tid < ROWP) { uu[tid] = 1.f; vv[tid] = 1.f; }
            __syncthreads();
        }
    }

    // ====== loss = ELN2 * sum_ij P * u_i v_j * A_ij  (C_nat = A * ELN2) ======
    // Each thread: u_rw * sum over its half-row of pr * v_j * A_ij; both halves add.
    float part = 0.f;
    {
        const float4* arow = (const float4*)(SC + rwc * COLP) + hf * RCH;
        const float4* v4   = ((const float4*)vv) + hf * RCH;
        float p0 = 0.f, p1 = 0.f, p2 = 0.f, p3 = 0.f;
        #pragma unroll
        for (int k = 0; k < RCH; ++k) {
            float4 p = pr[k]; float4 w = v4[k]; float4 a = arow[k];
            p0 += p.x * w.x * a.x;   // pad: p=0 kills A=1e30
            p1 += p.y * w.y * a.y;
            p2 += p.z * w.z * a.z;
            p3 += p.w * w.w * a.w;
        }
        if (rw < NPART) part = uu[rw] * ((p0 + p1) + (p2 + p3));
    }
    float tot = block_sum(part, red, tid);
    if (tid == 0) g_batch[b] = tot * ELN2;
}

__global__ void reduce_kernel(float* __restrict__ out, int B)
{
    __shared__ float red[256];
    int tid = threadIdx.x;
    float s = 0.f;
    for (int i = tid; i < B; i += 256) s += g_batch[i];
    red[tid] = s;
    __syncthreads();
    #pragma unroll
    for (int k = 128; k > 0; k >>= 1) {
        if (tid < k) red[tid] += red[tid + k];
        __syncthreads();
    }
    if (tid == 0) out[0] = red[0];
}

extern "C" void kernel_launch(void* const* d_in, const int* in_sizes, int n_in,
                              void* d_out, int out_size)
{
    const float* p_rec = (const float*)d_in[0];
    const float* p_tar = (const float*)d_in[1];
    int B = in_sizes[0] / (NPART * 3);
    if (B > 8192) B = 8192;

    size_t smem_bytes = (size_t)(ROWP * COLP + 14 * ROWP + NTHREADS) * sizeof(float);
    cudaFuncSetAttribute(sinkhorn_kernel,
                         cudaFuncAttributeMaxDynamicSharedMemorySize,
                         (int)smem_bytes);
    sinkhorn_kernel<<<B, NTHREADS, smem_bytes>>>(p_rec, p_tar);
    reduce_kernel<<<1, 256>>>((float*)d_out, B);
}

// round 11
// speedup vs baseline: 1.1411x; 1.1411x over previous
#include <cuda_runtime.h>
#include <math.h>

// Problem constants (B=2048, N=150; B derived from in_sizes)
#define NPART    150
#define ROWP     152
#define COLP     156            // row stride: conflict-free rows AND column walks
#define NCH      38             // float4 chunks covering [0,152)
#define RCH      19             // float4 chunks per half-row (76 floats)
#define NTHREADS 320            // mult phase: 152 rows x 2 halves = 304 active
#define ITERS    100
#define PEEL     3              // honest 2-pass log iters only; range safety proof:
                                // after honest F-update, row max of F+G-A >= la2-7.3 > -61
#define EPSR     1e-16f
#define INV_ELN2 28.853900817779268f   // 1/(0.05*ln2)
#define YPAD     1.0e4f

__device__ float g_batch[8192];

__device__ __forceinline__ float ex2f(float x) {
    float r; asm("ex2.approx.ftz.f32 %0, %1;" : "=f"(r) : "f"(x)); return r;
}
__device__ __forceinline__ float lg2f_(float x) {
    float r; asm("lg2.approx.f32 %0, %1;" : "=f"(r) : "f"(x)); return r;
}
// denser early absorbs (drift insurance after short peel), then every 15
__device__ __forceinline__ bool absorb_at(int it) {
    return (it == 8) | (it == 14) | (it == 20) | (it == 35) |
           (it == 50) | (it == 65) | (it == 80);
}

// block sum for NTHREADS=320
__device__ __forceinline__ float block_sum(float v, float* red, int tid) {
    red[tid] = v;
    __syncthreads();
    if (tid < 64) red[tid] += red[tid + 256];
    __syncthreads();
    #pragma unroll
    for (int s = 128; s > 0; s >>= 1) {
        if (tid < s) red[tid] += red[tid + s];
        __syncthreads();
    }
    float r = red[0];
    __syncthreads();
    return r;
}

extern __shared__ float smem[];

__global__ void __launch_bounds__(NTHREADS, 2)
sinkhorn_kernel(const float* __restrict__ p_rec, const float* __restrict__ p_tar)
{
    float* SC  = smem;                  // ROWP*COLP: cost A during peel, then P in place
    float* G2  = SC  + ROWP * COLP;
    float* F2  = G2  + ROWP;
    float* la2 = F2  + ROWP;
    float* lb2 = la2 + ROWP;
    float* uu  = lb2 + ROWP;            // multiplicative scalings
    float* vv  = uu  + ROWP;
    float* xe  = vv  + ROWP;
    float* xp  = xe  + ROWP;
    float* ye  = xp  + ROWP;
    float* yp  = ye  + ROWP;
    float* aL  = yp  + ROWP;
    float* bL  = aL  + ROWP;
    float* red = bL  + ROWP;            // NTHREADS floats

    const int b   = blockIdx.x;
    const int tid = threadIdx.x;
    const float PI_F  = 3.14159265358979323846f;
    const float TWOPI = 6.28318530717958647692f;

    // ---- load particles ----
    float px = 0.f, py = 0.f, pz = 0.f, qx = 0.f, qy = 0.f, qz = 0.f;
    if (tid < NPART) {
        const float* p = p_rec + (size_t)b * NPART * 3 + tid * 3;
        px = p[0]; py = p[1]; pz = p[2];
        const float* q = p_tar + (size_t)b * NPART * 3 + tid * 3;
        qx = q[0]; qy = q[1]; qz = q[2];
    }

    // ---- jet sums ----
    float jx = block_sum(px, red, tid);
    float jy = block_sum(py, red, tid);
    float jz = block_sum(pz, red, tid);
    float kx = block_sum(qx, red, tid);
    float ky = block_sum(qy, red, tid);
    float kz = block_sum(qz, red, tid);

    // ---- polar-rel coordinates ----
    float jpt  = sqrtf(jx * jx + jy * jy + EPSR);
    float jphi = atan2f(jy + EPSR, jx + EPSR);
    float jeta = asinhf(jz / (jpt + EPSR));
    float kpt  = sqrtf(kx * kx + ky * ky + EPSR);
    float kphi = atan2f(ky + EPSR, kx + EPSR);
    float keta = asinhf(kz / (kpt + EPSR));

    float ppt  = sqrtf(px * px + py * py + EPSR);
    float pphi = atan2f(py + EPSR, px + EPSR);
    float peta = asinhf(pz / (ppt + EPSR));
    float qpt  = sqrtf(qx * qx + qy * qy + EPSR);
    float qphi = atan2f(qy + EPSR, qx + EPSR);
    float qeta = asinhf(qz / (qpt + EPSR));

    float per = peta - jeta;
    float dpp = pphi - jphi + PI_F;
    float ppr = fmodf(dpp, TWOPI); if (ppr < 0.f) ppr += TWOPI; ppr -= PI_F;
    float pptr = ppt / (jpt + EPSR);

    float qer = qeta - keta;
    float dqq = qphi - kphi + PI_F;
    float qpr = fmodf(dqq, TWOPI); if (qpr < 0.f) qpr += TWOPI; qpr -= PI_F;
    float qptr = qpt / (kpt + EPSR);

    // ---- normalized marginals ----
    float Sa = block_sum(tid < NPART ? pptr : 0.f, red, tid);
    float Sb = block_sum(tid < NPART ? qptr : 0.f, red, tid);

    if (tid < NPART) {
        xe[tid] = per;  xp[tid] = ppr;
        ye[tid] = qer;  yp[tid] = qpr;
        float av = pptr / (Sa + EPSR) + EPSR;
        float bv = qptr / (Sb + EPSR) + EPSR;
        aL[tid]  = av;  bL[tid] = bv;
        la2[tid] = lg2f_(av);
        lb2[tid] = lg2f_(bv);
    } else if (tid < ROWP) {
        xe[tid] = YPAD; xp[tid] = YPAD;
        ye[tid] = YPAD; yp[tid] = YPAD;
        aL[tid] = 1.f;  bL[tid] = 1.f;
        la2[tid] = 0.f; lb2[tid] = 0.f;
    }
    if (tid < ROWP) { G2[tid] = 0.f; F2[tid] = 0.f; }
    __syncthreads();

    // ---- cost matrix A (pad = 1e30 kills pad terms in peel) ----
    for (int idx = tid; idx < ROWP * COLP; idx += NTHREADS) {
        int i = idx / COLP;
        int j = idx - i * COLP;
        float v = 1e30f;
        if (i < NPART && j < NPART) {
            float de = xe[i] - ye[j];
            float dp = xp[i] - yp[j];
            v = sqrtf(de * de + dp * dp + EPSR) * INV_ELN2;
        }
        SC[idx] = v;
    }
    __syncthreads();

    // ================= Phase 1: short honest log-domain peel =================
    for (int it = 0; it < PEEL; ++it) {
        if (tid < NPART) {
            const float4* crow = (const float4*)(SC + tid * COLP);
            const float4* gp   = (const float4*)G2;
            float m0 = -3.4e38f, m1 = -3.4e38f, m2 = -3.4e38f, m3 = -3.4e38f;
            #pragma unroll 2
            for (int k = 0; k < NCH; ++k) {
                float4 c = crow[k]; float4 g = gp[k];
                m0 = fmaxf(m0, g.x - c.x); m1 = fmaxf(m1, g.y - c.y);
                m2 = fmaxf(m2, g.z - c.z); m3 = fmaxf(m3, g.w - c.w);
            }
            float m = fmaxf(fmaxf(m0, m1), fmaxf(m2, m3));
            float s0 = 0.f, s1 = 0.f, s2 = 0.f, s3 = 0.f;
            #pragma unroll 2
            for (int k = 0; k < NCH; ++k) {
                float4 c = crow[k]; float4 g = gp[k];
                s0 += ex2f(g.x - c.x - m); s1 += ex2f(g.y - c.y - m);
                s2 += ex2f(g.z - c.z - m); s3 += ex2f(g.w - c.w - m);
            }
            F2[tid] = la2[tid] - (m + lg2f_((s0 + s1) + (s2 + s3)));
        }
        __syncthreads();

        if (tid < NPART) {
            const float*  ccol = SC + tid;
            const float4* fp   = (const float4*)F2;
            float m0 = -3.4e38f, m1 = -3.4e38f, m2 = -3.4e38f, m3 = -3.4e38f;
            #pragma unroll 2
            for (int k = 0; k < NCH; ++k) {
                float4 f = fp[k];
                const float* cb = ccol + 4 * k * COLP;
                m0 = fmaxf(m0, f.x - cb[0]);
                m1 = fmaxf(m1, f.y - cb[COLP]);
                m2 = fmaxf(m2, f.z - cb[2 * COLP]);
                m3 = fmaxf(m3, f.w - cb[3 * COLP]);
            }
            float m = fmaxf(fmaxf(m0, m1), fmaxf(m2, m3));
            float s0 = 0.f, s1 = 0.f, s2 = 0.f, s3 = 0.f;
            #pragma unroll 2
            for (int k = 0; k < NCH; ++k) {
                float4 f = fp[k];
                const float* cb = ccol + 4 * k * COLP;
                s0 += ex2f(f.x - cb[0]        - m);
                s1 += ex2f(f.y - cb[COLP]     - m);
                s2 += ex2f(f.z - cb[2 * COLP] - m);
                s3 += ex2f(f.w - cb[3 * COLP] - m);
            }
            G2[tid] = lb2[tid] - (m + lg2f_((s0 + s1) + (s2 + s3)));
        }
        __syncthreads();
    }

    // ================= Build P = 2^(F2_i + G2_j - A_ij) in place =================
    if (tid < NPART) {
        float4* prow = (float4*)(SC + tid * COLP);
        const float4* gp = (const float4*)G2;
        float fi = F2[tid];
        #pragma unroll 2
        for (int k = 0; k < NCH; ++k) {
            float4 c = prow[k]; float4 g = gp[k];
            float4 o;
            o.x = ex2f(fi + g.x - c.x);   // pad cols (c=1e30) -> 0
            o.y = ex2f(fi + g.y - c.y);
            o.z = ex2f(fi + g.z - c.z);
            o.w = ex2f(fi + g.w - c.w);
            prow[k] = o;
        }
    } else if (tid < ROWP) {
        float4* prow = (float4*)(SC + tid * COLP);
        float4 z = make_float4(0.f, 0.f, 0.f, 0.f);
        #pragma unroll 2
        for (int k = 0; k < NCH; ++k) prow[k] = z;    // zero pad rows 150,151
    }
    if (tid < ROWP) { uu[tid] = 1.f; vv[tid] = 1.f; }
    __syncthreads();

    // ---- mult-phase mapping: 2 threads per row/column ----
    const int rw  = tid >> 1;                          // 0..159
    const int hf  = tid & 1;                           // half: [hf*76, hf*76+76)
    const int rwc = (rw < ROWP - 1) ? rw : (ROWP - 1); // clamp keeps lanes converged

    // register cache of this thread's half P row (pad rows hold zeros)
    float4 pr[RCH];
    {
        const float4* prow = (const float4*)(SC + rwc * COLP) + hf * RCH;
        #pragma unroll
        for (int k = 0; k < RCH; ++k) pr[k] = prow[k];
    }

    // ================= Phase 2: multiplicative iterations =================
    for (int it = PEEL; it < ITERS; ++it) {
        // ---- u-update from registers: u_i = a_i / sum_j P[i][j] v_j ----
        {
            const float4* v4 = ((const float4*)vv) + hf * RCH;
            float r0 = 0.f, r1 = 0.f, r2 = 0.f, r3 = 0.f;
            #pragma unroll
            for (int k = 0; k < RCH; ++k) {
                float4 p = pr[k]; float4 w = v4[k];
                r0 += p.x * w.x; r1 += p.y * w.y;
                r2 += p.z * w.z; r3 += p.w * w.w;
            }
            float r = (r0 + r1) + (r2 + r3);
            r += __shfl_xor_sync(0xFFFFFFFF, r, 1);
            if (hf == 0 && rw < NPART) uu[rw] = __fdividef(aL[rw], r);
        }
        __syncthreads();

        // ---- v-update from smem columns: v_j = b_j / sum_i P[i][j] u_i ----
        {
            const float* pcol = SC + rwc + (hf * 76) * COLP;
            const float* up   = uu + hf * 76;
            float c0 = 0.f, c1 = 0.f;
            #pragma unroll 4
            for (int r = 0; r < 76; r += 2) {
                c0 += pcol[r * COLP]       * up[r];
                c1 += pcol[(r + 1) * COLP] * up[r + 1];
            }
            float c = c0 + c1;
            c += __shfl_xor_sync(0xFFFFFFFF, c, 1);
            if (hf == 0 && rw < NPART) vv[rw] = __fdividef(bL[rw], c);
        }
        __syncthreads();

        // ---- absorption (denser early, every 15 later) ----
        if (absorb_at(it)) {
            if (tid < NPART) {
                F2[tid] += lg2f_(uu[tid]);
                G2[tid] += lg2f_(vv[tid]);
            }
            __syncthreads();
            if (tid < NPART) {
                float4* prow = (float4*)(SC + tid * COLP);
                const float4* ge4 = (const float4*)ye;
                const float4* gp4 = (const float4*)yp;
                const float4* gg4 = (const float4*)G2;
                float fi  = F2[tid];
                float xei = xe[tid], xpi = xp[tid];
                #pragma unroll 2
                for (int k = 0; k < NCH; ++k) {
                    float4 e = ge4[k], h = gp4[k], g = gg4[k];
                    float4 o;
                    {
                        float de = xei - e.x, dp = xpi - h.x;
                        float A = sqrtf(de * de + dp * dp + EPSR) * INV_ELN2;
                        o.x = ex2f(fi + g.x - A);
                    }
                    {
                        float de = xei - e.y, dp = xpi - h.y;
                        float A = sqrtf(de * de + dp * dp + EPSR) * INV_ELN2;
                        o.y = ex2f(fi + g.y - A);
                    }
                    {
                        float de = xei - e.z, dp = xpi - h.z;
                        float A = sqrtf(de * de + dp * dp + EPSR) * INV_ELN2;
                        o.z = ex2f(fi + g.z - A);
                    }
                    {
                        float de = xei - e.w, dp = xpi - h.w;
                        float A = sqrtf(de * de + dp * dp + EPSR) * INV_ELN2;
                        o.w = ex2f(fi + g.w - A);
                    }
                    prow[k] = o;   // pad cols: ye=YPAD -> A huge -> 0
                }
            }
            __syncthreads();
            if (tid < ROWP) { uu[tid] = 1.f; vv[tid] = 1.f; }
            __syncthreads();
            // reload register cache from rebuilt P
            {
                const float4* prow = (const float4*)(SC + rwc * COLP) + hf * RCH;
                #pragma unroll
                for (int k = 0; k < RCH; ++k) pr[k] = prow[k];
            }
        }
    }

    // ================= loss = sum_ij P*u_i*v_j * C_ij (C in nat units) =================
    float part = 0.f;
    if (tid < NPART) {
        const float4* prow = (const float4*)(SC + tid * COLP);
        const float4* w4   = (const float4*)vv;
        const float4* ge4  = (const float4*)ye;
        const float4* gp4  = (const float4*)yp;
        float xei = xe[tid], xpi = xp[tid];
        float p0 = 0.f, p1 = 0.f, p2 = 0.f, p3 = 0.f;
        #pragma unroll 2
        for (int k = 0; k < NCH; ++k) {
            float4 p = prow[k]; float4 w = w4[k];
            float4 e = ge4[k],  h = gp4[k];
            {
                float de = xei - e.x, dp = xpi - h.x;
                p0 += p.x * w.x * sqrtf(de * de + dp * dp + EPSR);
            }
            {
                float de = xei - e.y, dp = xpi - h.y;
                p1 += p.y * w.y * sqrtf(de * de + dp * dp + EPSR);
            }
            {
                float de = xei - e.z, dp = xpi - h.z;
                p2 += p.z * w.z * sqrtf(de * de + dp * dp + EPSR);
            }
            {
                float de = xei - e.w, dp = xpi - h.w;
                p3 += p.w * w.w * sqrtf(de * de + dp * dp + EPSR);
            }
        }
        part = uu[tid] * ((p0 + p1) + (p2 + p3));
    }
    float tot = block_sum(part, red, tid);
    if (tid == 0) g_batch[b] = tot;
}

__global__ void reduce_kernel(float* __restrict__ out, int B)
{
    __shared__ float red[256];
    int tid = threadIdx.x;
    float s = 0.f;
    for (int i = tid; i < B; i += 256) s += g_batch[i];
    red[tid] = s;
    __syncthreads();
    #pragma unroll
    for (int k = 128; k > 0; k >>= 1) {
        if (tid < k) red[tid] += red[tid + k];
        __syncthreads();
    }
    if (tid == 0) out[0] = red[0];
}

extern "C" void kernel_launch(void* const* d_in, const int* in_sizes, int n_in,
                              void* d_out, int out_size)
{
    const float* p_rec = (const float*)d_in[0];
    const float* p_tar = (const float*)d_in[1];
    int B = in_sizes[0] / (NPART * 3);
    if (B > 8192) B = 8192;

    size_t smem_bytes = (size_t)(ROWP * COLP + 12 * ROWP + NTHREADS) * sizeof(float);
    cudaFuncSetAttribute(sinkhorn_kernel,
                         cudaFuncAttributeMaxDynamicSharedMemorySize,
                         (int)smem_bytes);
    sinkhorn_kernel<<<B, NTHREADS, smem_bytes>>>(p_rec, p_tar);
    reduce_kernel<<<1, 256>>>((float*)d_out, B);
}

// round 12
// speedup vs baseline: 1.2071x; 1.0578x over previous
#include <cuda_runtime.h>
#include <math.h>

// Problem constants (B=2048, N=150; B derived from in_sizes)
#define NPART    150
#define ROWP     152
#define COLP     156            // peel-phase A row stride (row-major, conflict-free)
#define COLP2    164            // PT row stride: lanes (rw,hf) -> first bank 4rw+16hf,
                                // all 8 lanes/phase disjoint 4-bank groups (LDS.128 CF)
#define NCH      38             // float4 chunks covering [0,152) (peel)
#define RCH      19             // pr register chunks: j in [hf*76, hf*76+76)
#define VCH      20             // v-update chunks: i in [hf*80, hf*80+80)
#define VROW     160            // vector array length (pad [150,160))
#define NTHREADS 320
#define ITERS    100
#define PEEL     3              // honest 2-pass log iters (range-safety proven R11)
#define EPSR     1e-16f
#define INV_ELN2 28.853900817779268f   // 1/(0.05*ln2)
#define YPAD     1.0e4f

__device__ float g_batch[8192];

__device__ __forceinline__ float ex2f(float x) {
    float r; asm("ex2.approx.ftz.f32 %0, %1;" : "=f"(r) : "f"(x)); return r;
}
__device__ __forceinline__ float lg2f_(float x) {
    float r; asm("lg2.approx.f32 %0, %1;" : "=f"(r) : "f"(x)); return r;
}
__device__ __forceinline__ bool absorb_at(int it) {
    return (it == 8) | (it == 14) | (it == 20) | (it == 35) |
           (it == 50) | (it == 65) | (it == 80);
}

// block sum for NTHREADS=320
__device__ __forceinline__ float block_sum(float v, float* red, int tid) {
    red[tid] = v;
    __syncthreads();
    if (tid < 64) red[tid] += red[tid + 256];
    __syncthreads();
    #pragma unroll
    for (int s = 128; s > 0; s >>= 1) {
        if (tid < s) red[tid] += red[tid + s];
        __syncthreads();
    }
    float r = red[0];
    __syncthreads();
    return r;
}

// Rebuild PT[j][i] = 2^(F2_i + G2_j - A_ij) from coordinates.
// Thread (rw,hf): row j=rw, i in [hf*80, hf*80+80); i>=152 zeroed.
__device__ __forceinline__ void rebuild_PT(
    float* SC, const float* xe, const float* xp,
    const float* ye, const float* yp,
    const float* F2, const float* G2, int rw, int hf)
{
    if (rw >= ROWP) return;
    float4* dst = (float4*)(SC + rw * COLP2) + hf * VCH;
    const float4* xe4 = ((const float4*)xe) + hf * VCH;
    const float4* xp4 = ((const float4*)xp) + hf * VCH;
    const float4* f4  = ((const float4*)F2) + hf * VCH;
    float gj  = G2[rw];
    float yej = ye[rw], ypj = yp[rw];
    #pragma unroll
    for (int k = 0; k < VCH; ++k) {
        float4 o = make_float4(0.f, 0.f, 0.f, 0.f);
        if (hf == 0 || k < 18) {         // i < 152 only
            float4 e = xe4[k], p = xp4[k], f = f4[k];
            float de, dp;
            de = e.x - yej; dp = p.x - ypj;
            o.x = ex2f(f.x + gj - sqrtf(de * de + dp * dp + EPSR) * INV_ELN2);
            de = e.y - yej; dp = p.y - ypj;
            o.y = ex2f(f.y + gj - sqrtf(de * de + dp * dp + EPSR) * INV_ELN2);
            de = e.z - yej; dp = p.z - ypj;
            o.z = ex2f(f.z + gj - sqrtf(de * de + dp * dp + EPSR) * INV_ELN2);
            de = e.w - yej; dp = p.w - ypj;
            o.w = ex2f(f.w + gj - sqrtf(de * de + dp * dp + EPSR) * INV_ELN2);
        }
        dst[k] = o;
    }
}

extern __shared__ float smem[];

__global__ void __launch_bounds__(NTHREADS, 2)
sinkhorn_kernel(const float* __restrict__ p_rec, const float* __restrict__ p_tar)
{
    float* SC  = smem;                  // peel: A (stride COLP); mult: PT (stride COLP2)
    float* G2  = SC  + ROWP * COLP2;    // all vectors VROW floats (16B-aligned)
    float* F2  = G2  + VROW;
    float* la2 = F2  + VROW;
    float* lb2 = la2 + VROW;
    float* uu  = lb2 + VROW;
    float* vv  = uu  + VROW;
    float* xe  = vv  + VROW;
    float* xp  = xe  + VROW;
    float* ye  = xp  + VROW;
    float* yp  = ye  + VROW;
    float* aL  = yp  + VROW;
    float* bL  = aL  + VROW;
    float* red = bL  + VROW;            // NTHREADS floats

    const int b   = blockIdx.x;
    const int tid = threadIdx.x;
    const float PI_F  = 3.14159265358979323846f;
    const float TWOPI = 6.28318530717958647692f;

    // ---- load particles ----
    float px = 0.f, py = 0.f, pz = 0.f, qx = 0.f, qy = 0.f, qz = 0.f;
    if (tid < NPART) {
        const float* p = p_rec + (size_t)b * NPART * 3 + tid * 3;
        px = p[0]; py = p[1]; pz = p[2];
        const float* q = p_tar + (size_t)b * NPART * 3 + tid * 3;
        qx = q[0]; qy = q[1]; qz = q[2];
    }

    // ---- jet sums ----
    float jx = block_sum(px, red, tid);
    float jy = block_sum(py, red, tid);
    float jz = block_sum(pz, red, tid);
    float kx = block_sum(qx, red, tid);
    float ky = block_sum(qy, red, tid);
    float kz = block_sum(qz, red, tid);

    // ---- polar-rel coordinates ----
    float jpt  = sqrtf(jx * jx + jy * jy + EPSR);
    float jphi = atan2f(jy + EPSR, jx + EPSR);
    float jeta = asinhf(jz / (jpt + EPSR));
    float kpt  = sqrtf(kx * kx + ky * ky + EPSR);
    float kphi = atan2f(ky + EPSR, kx + EPSR);
    float keta = asinhf(kz / (kpt + EPSR));

    float ppt  = sqrtf(px * px + py * py + EPSR);
    float pphi = atan2f(py + EPSR, px + EPSR);
    float peta = asinhf(pz / (ppt + EPSR));
    float qpt  = sqrtf(qx * qx + qy * qy + EPSR);
    float qphi = atan2f(qy + EPSR, qx + EPSR);
    float qeta = asinhf(qz / (qpt + EPSR));

    float per = peta - jeta;
    float dpp = pphi - jphi + PI_F;
    float ppr = fmodf(dpp, TWOPI); if (ppr < 0.f) ppr += TWOPI; ppr -= PI_F;
    float pptr = ppt / (jpt + EPSR);

    float qer = qeta - keta;
    float dqq = qphi - kphi + PI_F;
    float qpr = fmodf(dqq, TWOPI); if (qpr < 0.f) qpr += TWOPI; qpr -= PI_F;
    float qptr = qpt / (kpt + EPSR);

    // ---- normalized marginals ----
    float Sa = block_sum(tid < NPART ? pptr : 0.f, red, tid);
    float Sb = block_sum(tid < NPART ? qptr : 0.f, red, tid);

    if (tid < NPART) {
        xe[tid] = per;  xp[tid] = ppr;
        ye[tid] = qer;  yp[tid] = qpr;
        float av = pptr / (Sa + EPSR) + EPSR;
        float bv = qptr / (Sb + EPSR) + EPSR;
        aL[tid]  = av;  bL[tid] = bv;
        la2[tid] = lg2f_(av);
        lb2[tid] = lg2f_(bv);
    } else if (tid < VROW) {
        xe[tid] = YPAD; xp[tid] = YPAD;
        ye[tid] = YPAD; yp[tid] = YPAD;
        aL[tid] = 1.f;  bL[tid] = 1.f;
        la2[tid] = 0.f; lb2[tid] = 0.f;
    }
    if (tid < VROW) { G2[tid] = 0.f; F2[tid] = 0.f; uu[tid] = 1.f; vv[tid] = 1.f; }
    __syncthreads();

    // ---- cost matrix A row-major, stride COLP (peel only; pad = 1e30) ----
    for (int idx = tid; idx < ROWP * COLP; idx += NTHREADS) {
        int i = idx / COLP;
        int j = idx - i * COLP;
        float v = 1e30f;
        if (i < NPART && j < NPART) {
            float de = xe[i] - ye[j];
            float dp = xp[i] - yp[j];
            v = sqrtf(de * de + dp * dp + EPSR) * INV_ELN2;
        }
        SC[idx] = v;
    }
    __syncthreads();

    // ================= Phase 1: short honest log-domain peel =================
    for (int it = 0; it < PEEL; ++it) {
        if (tid < NPART) {
            const float4* crow = (const float4*)(SC + tid * COLP);
            const float4* gp   = (const float4*)G2;
            float m0 = -3.4e38f, m1 = -3.4e38f, m2 = -3.4e38f, m3 = -3.4e38f;
            #pragma unroll 2
            for (int k = 0; k < NCH; ++k) {
                float4 c = crow[k]; float4 g = gp[k];
                m0 = fmaxf(m0, g.x - c.x); m1 = fmaxf(m1, g.y - c.y);
                m2 = fmaxf(m2, g.z - c.z); m3 = fmaxf(m3, g.w - c.w);
            }
            float m = fmaxf(fmaxf(m0, m1), fmaxf(m2, m3));
            float s0 = 0.f, s1 = 0.f, s2 = 0.f, s3 = 0.f;
            #pragma unroll 2
            for (int k = 0; k < NCH; ++k) {
                float4 c = crow[k]; float4 g = gp[k];
                s0 += ex2f(g.x - c.x - m); s1 += ex2f(g.y - c.y - m);
                s2 += ex2f(g.z - c.z - m); s3 += ex2f(g.w - c.w - m);
            }
            F2[tid] = la2[tid] - (m + lg2f_((s0 + s1) + (s2 + s3)));
        }
        __syncthreads();

        if (tid < NPART) {
            const float*  ccol = SC + tid;
            const float4* fp   = (const float4*)F2;
            float m0 = -3.4e38f, m1 = -3.4e38f, m2 = -3.4e38f, m3 = -3.4e38f;
            #pragma unroll 2
            for (int k = 0; k < NCH; ++k) {
                float4 f = fp[k];
                const float* cb = ccol + 4 * k * COLP;
                m0 = fmaxf(m0, f.x - cb[0]);
                m1 = fmaxf(m1, f.y - cb[COLP]);
                m2 = fmaxf(m2, f.z - cb[2 * COLP]);
                m3 = fmaxf(m3, f.w - cb[3 * COLP]);
            }
            float m = fmaxf(fmaxf(m0, m1), fmaxf(m2, m3));
            float s0 = 0.f, s1 = 0.f, s2 = 0.f, s3 = 0.f;
            #pragma unroll 2
            for (int k = 0; k < NCH; ++k) {
                float4 f = fp[k];
                const float* cb = ccol + 4 * k * COLP;
                s0 += ex2f(f.x - cb[0]        - m);
                s1 += ex2f(f.y - cb[COLP]     - m);
                s2 += ex2f(f.z - cb[2 * COLP] - m);
                s3 += ex2f(f.w - cb[3 * COLP] - m);
            }
            G2[tid] = lb2[tid] - (m + lg2f_((s0 + s1) + (s2 + s3)));
        }
        __syncthreads();
    }

    // ---- mult-phase mapping: 2 threads per row/column ----
    const int rw  = tid >> 1;                          // 0..159
    const int hf  = tid & 1;
    const int rwc = (rw < ROWP - 1) ? rw : (ROWP - 1); // clamp keeps lanes converged

    // ================= Build PT (transpose of P) in place, from coordinates =================
    rebuild_PT(SC, xe, xp, ye, yp, F2, G2, rw, hf);
    __syncthreads();

    // register cache: pr[k] = P[rw][j] = PT[j][rw],  j = hf*76 + 4k + {0..3}
    float4 pr[RCH];
    {
        const float* base = SC + rwc + (hf * 76) * COLP2;
        #pragma unroll
        for (int k = 0; k < RCH; ++k) {
            pr[k].x = base[(4 * k + 0) * COLP2];
            pr[k].y = base[(4 * k + 1) * COLP2];
            pr[k].z = base[(4 * k + 2) * COLP2];
            pr[k].w = base[(4 * k + 3) * COLP2];
        }
    }

    // ================= Phase 2: multiplicative iterations =================
    for (int it = PEEL; it < ITERS; ++it) {
        // ---- u-update: u_i = a_i / sum_j P[i][j] v_j  (registers + broadcast v) ----
        {
            const float4* v4 = ((const float4*)vv) + hf * RCH;
            float r0 = 0.f, r1 = 0.f, r2 = 0.f, r3 = 0.f;
            #pragma unroll
            for (int k = 0; k < RCH; ++k) {
                float4 p = pr[k]; float4 w = v4[k];
                r0 += p.x * w.x; r1 += p.y * w.y;
                r2 += p.z * w.z; r3 += p.w * w.w;
            }
            float r = (r0 + r1) + (r2 + r3);
            r += __shfl_xor_sync(0xFFFFFFFF, r, 1);
            if (hf == 0 && rw < NPART) uu[rw] = __fdividef(aL[rw], r);
        }
        __syncthreads();

        // ---- v-update: v_j = b_j / sum_i PT[j][i] u_i  (LDS.128 rows + broadcast u) ----
        {
            const float4* ptrow = (const float4*)(SC + rwc * COLP2) + hf * VCH;
            const float4* u4    = ((const float4*)uu) + hf * VCH;
            float c0 = 0.f, c1 = 0.f, c2 = 0.f, c3 = 0.f;
            #pragma unroll
            for (int k = 0; k < VCH; ++k) {
                float4 p = ptrow[k]; float4 w = u4[k];
                c0 += p.x * w.x; c1 += p.y * w.y;
                c2 += p.z * w.z; c3 += p.w * w.w;
            }
            float c = (c0 + c1) + (c2 + c3);
            c += __shfl_xor_sync(0xFFFFFFFF, c, 1);
            if (hf == 0 && rw < NPART) vv[rw] = __fdividef(bL[rw], c);
        }
        __syncthreads();

        // ---- absorption: fold u,v into F2,G2; rebuild PT; reload pr ----
        if (absorb_at(it)) {
            if (tid < NPART) {
                F2[tid] += lg2f_(uu[tid]);
                G2[tid] += lg2f_(vv[tid]);
            }
            __syncthreads();
            rebuild_PT(SC, xe, xp, ye, yp, F2, G2, rw, hf);
            __syncthreads();
            if (tid < VROW) { uu[tid] = 1.f; vv[tid] = 1.f; }
            __syncthreads();
            {
                const float* base = SC + rwc + (hf * 76) * COLP2;
                #pragma unroll
                for (int k = 0; k < RCH; ++k) {
                    pr[k].x = base[(4 * k + 0) * COLP2];
                    pr[k].y = base[(4 * k + 1) * COLP2];
                    pr[k].z = base[(4 * k + 2) * COLP2];
                    pr[k].w = base[(4 * k + 3) * COLP2];
                }
            }
        }
    }

    // ================= loss = sum_ij P*u_i*v_j * C_ij (C nat units, from registers) ====
    float part = 0.f;
    {
        const float4* v4  = ((const float4*)vv) + hf * RCH;
        const float4* ye4 = ((const float4*)ye) + hf * RCH;
        const float4* yp4 = ((const float4*)yp) + hf * RCH;
        float xei = xe[rwc], xpi = xp[rwc];
        float p0 = 0.f, p1 = 0.f, p2 = 0.f, p3 = 0.f;
        #pragma unroll 2
        for (int k = 0; k < RCH; ++k) {
            float4 p = pr[k]; float4 w = v4[k];
            float4 e = ye4[k], h = yp4[k];
            {
                float de = xei - e.x, dp = xpi - h.x;
                p0 += p.x * w.x * sqrtf(de * de + dp * dp + EPSR);
            }
            {
                float de = xei - e.y, dp = xpi - h.y;
                p1 += p.y * w.y * sqrtf(de * de + dp * dp + EPSR);
            }
            {
                float de = xei - e.z, dp = xpi - h.z;
                p2 += p.z * w.z * sqrtf(de * de + dp * dp + EPSR);
            }
            {
                float de = xei - e.w, dp = xpi - h.w;
                p3 += p.w * w.w * sqrtf(de * de + dp * dp + EPSR);
            }
        }
        if (rw < NPART) part = uu[rw] * ((p0 + p1) + (p2 + p3));
    }
    float tot = block_sum(part, red, tid);
    if (tid == 0) g_batch[b] = tot;
}

__global__ void reduce_kernel(float* __restrict__ out, int B)
{
    __shared__ float red[256];
    int tid = threadIdx.x;
    float s = 0.f;
    for (int i = tid; i < B; i += 256) s += g_batch[i];
    red[tid] = s;
    __syncthreads();
    #pragma unroll
    for (int k = 128; k > 0; k >>= 1) {
        if (tid < k) red[tid] += red[tid + k];
        __syncthreads();
    }
    if (tid == 0) out[0] = red[0];
}

extern "C" void kernel_launch(void* const* d_in, const int* in_sizes, int n_in,
                              void* d_out, int out_size)
{
    const float* p_rec = (const float*)d_in[0];
    const float* p_tar = (const float*)d_in[1];
    int B = in_sizes[0] / (NPART * 3);
    if (B > 8192) B = 8192;

    size_t smem_bytes = (size_t)(ROWP * COLP2 + 12 * VROW + NTHREADS) * sizeof(float);
    cudaFuncSetAttribute(sinkhorn_kernel,
                         cudaFuncAttributeMaxDynamicSharedMemorySize,
                         (int)smem_bytes);
    sinkhorn_kernel<<<B, NTHREADS, smem_bytes>>>(p_rec, p_tar);
    reduce_kernel<<<1, 256>>>((float*)d_out, B);
}